// round 5
// baseline (speedup 1.0000x reference)
#include <cuda_runtime.h>
#include <cuda_bf16.h>
#include <cstdint>
#include <math.h>

#define BATCH 8
#define SEQ   2048
#define CH    512
#define KSZ   512
#define VSZ   512
#define OUTC  1024
#define MROWS (BATCH * SEQ)
#define SCALE 0.044194173824159216f  /* 1/sqrt(512) */

// ------------------------- scratch (static device) -------------------------
static __device__ __nv_bfloat16 g_xh[(size_t)MROWS * CH];
static __device__ __nv_bfloat16 g_xl[(size_t)MROWS * CH];
static __device__ __nv_bfloat16 g_wh[3 * CH * CH];
static __device__ __nv_bfloat16 g_wl[3 * CH * CH];
static __device__ __nv_bfloat16 g_qh[(size_t)MROWS * KSZ];
static __device__ __nv_bfloat16 g_ql[(size_t)MROWS * KSZ];
static __device__ __nv_bfloat16 g_kh[(size_t)MROWS * KSZ];
static __device__ __nv_bfloat16 g_kl[(size_t)MROWS * KSZ];
static __device__ float         g_v [(size_t)MROWS * VSZ];
static __device__ __nv_bfloat16 g_vth[(size_t)BATCH * VSZ * SEQ];  // transposed V/colsum
static __device__ __nv_bfloat16 g_vtl[(size_t)BATCH * VSZ * SEQ];
static __device__ __nv_bfloat16 g_eh[(size_t)BATCH * SEQ * SEQ];
static __device__ __nv_bfloat16 g_el[(size_t)BATCH * SEQ * SEQ];
static __device__ float         g_colsum[BATCH * SEQ];

// ------------------------- smem layout ------------------------------------
// two buffers of 4 planes (Ah, Al, Bh, Bl), each plane [128][40] bf16 = 10240B
#define PL      10240
#define BUFSZ   40960
#define SM_AUX  (2 * BUFSZ)          // 512 B: bias / column sums
#define SMEM_BYTES (2 * BUFSZ + 512)
#define LDS_S   40                    // padded smem row stride (elements)

// ------------------------- ptx helpers ------------------------------------
__device__ __forceinline__ uint32_t smem_u32(const void* p) {
    uint32_t a;
    asm("{ .reg .u64 t; cvta.to.shared.u64 t, %1; cvt.u32.u64 %0, t; }" : "=r"(a) : "l"(p));
    return a;
}

#define CP_ASYNC16(dst, src) \
    asm volatile("cp.async.cg.shared.global [%0], [%1], 16;" :: "r"(dst), "l"(src))
#define CP_COMMIT()  asm volatile("cp.async.commit_group;")
#define CP_WAIT1()   asm volatile("cp.async.wait_group 1;")
#define CP_WAIT0()   asm volatile("cp.async.wait_group 0;")

#define LDSM4(r, a) \
    asm volatile("ldmatrix.sync.aligned.m8n8.x4.shared.b16 {%0,%1,%2,%3}, [%4];" \
                 : "=r"((r)[0]), "=r"((r)[1]), "=r"((r)[2]), "=r"((r)[3]) : "r"(a))

__device__ __forceinline__ void mma16816(float* c, const uint32_t* a, uint32_t b0, uint32_t b1) {
    asm volatile(
        "mma.sync.aligned.m16n8k16.row.col.f32.bf16.bf16.f32 "
        "{%0,%1,%2,%3}, {%4,%5,%6,%7}, {%8,%9}, {%0,%1,%2,%3};"
        : "+f"(c[0]), "+f"(c[1]), "+f"(c[2]), "+f"(c[3])
        : "r"(a[0]), "r"(a[1]), "r"(a[2]), "r"(a[3]), "r"(b0), "r"(b1));
}

// split fp32 -> (hi, lo) bf16
__device__ __forceinline__ void split2(float x, float y, uint32_t& H, uint32_t& L) {
    __nv_bfloat16 hx = __float2bfloat16_rn(x);
    __nv_bfloat16 hy = __float2bfloat16_rn(y);
    __nv_bfloat16 lx = __float2bfloat16_rn(x - __bfloat162float(hx));
    __nv_bfloat16 ly = __float2bfloat16_rn(y - __bfloat162float(hy));
    H = (uint32_t)__bfloat16_as_ushort(hx) | ((uint32_t)__bfloat16_as_ushort(hy) << 16);
    L = (uint32_t)__bfloat16_as_ushort(lx) | ((uint32_t)__bfloat16_as_ushort(ly) << 16);
}

__device__ __forceinline__ void split_pack8(const float* x, uint4& H, uint4& L) {
    uint32_t h[4], l[4];
#pragma unroll
    for (int q = 0; q < 4; q++) split2(x[2 * q], x[2 * q + 1], h[q], l[q]);
    H = make_uint4(h[0], h[1], h[2], h[3]);
    L = make_uint4(l[0], l[1], l[2], l[3]);
}

// ---------------------------------------------------------------------------
// chunk loader: 512 threads, 4 planes x 128 rows x 64B (k-chunk = 32 bf16)
// ---------------------------------------------------------------------------
__device__ __forceinline__ void load_chunk(
    uint32_t sbuf, int t,
    const __nv_bfloat16* Ah, const __nv_bfloat16* Al, int lda,
    const __nv_bfloat16* Bh, const __nv_bfloat16* Bl, int ldb, int k0)
{
    const int row = t >> 2, seg = t & 3;
    const size_t goA = (size_t)row * lda + k0 + seg * 8;
    const size_t goB = (size_t)row * ldb + k0 + seg * 8;
    const uint32_t so = sbuf + row * (LDS_S * 2) + seg * 16;
    CP_ASYNC16(so,          Ah + goA);
    CP_ASYNC16(so + PL,     Al + goA);
    CP_ASYNC16(so + 2 * PL, Bh + goB);
    CP_ASYNC16(so + 3 * PL, Bl + goB);
}

// ---------------------------------------------------------------------------
// compute one 32-K chunk: warp tile 32x32, bf16x3 (hh + hl + lh)
// ---------------------------------------------------------------------------
__device__ __forceinline__ void compute_chunk(
    uint32_t sbuf, int wm, int wn, int lane, float acc[2][4][4])
{
    const int lm = lane & 15, lk = lane >> 4;
#pragma unroll
    for (int ks = 0; ks < 2; ks++) {
        uint32_t ah[2][4], al[2][4];
#pragma unroll
        for (int m2 = 0; m2 < 2; m2++) {
            uint32_t ad = sbuf + (wm * 32 + m2 * 16 + lm) * (LDS_S * 2) + (ks * 16 + lk * 8) * 2;
            LDSM4(ah[m2], ad);
            LDSM4(al[m2], ad + PL);
        }
        uint32_t bh[2][4], bl[2][4];
#pragma unroll
        for (int np = 0; np < 2; np++) {
            uint32_t bd = sbuf + 2 * PL + (wn * 32 + np * 16 + lm) * (LDS_S * 2) + (ks * 16 + lk * 8) * 2;
            LDSM4(bh[np], bd);
            LDSM4(bl[np], bd + PL);
        }
#pragma unroll
        for (int m2 = 0; m2 < 2; m2++)
#pragma unroll
            for (int n = 0; n < 4; n++) {
                const int np = n >> 1, sel = n & 1;
                mma16816(acc[m2][n], ah[m2], bh[np][sel], bh[np][sel + 2]);
                mma16816(acc[m2][n], ah[m2], bl[np][sel], bl[np][sel + 2]);
                mma16816(acc[m2][n], al[m2], bh[np][sel], bh[np][sel + 2]);
            }
    }
}

// ---------------------------------------------------------------------------
// full double-buffered mainloop
// ---------------------------------------------------------------------------
__device__ __forceinline__ void gemm_loop(
    uint32_t sb, int t,
    const __nv_bfloat16* Ah, const __nv_bfloat16* Al, int lda,
    const __nv_bfloat16* Bh, const __nv_bfloat16* Bl, int ldb,
    int NC, float acc[2][4][4])
{
    const int wid = t >> 5, lane = t & 31;
    const int wm = wid & 3, wn = wid >> 2;

    load_chunk(sb, t, Ah, Al, lda, Bh, Bl, ldb, 0);
    CP_COMMIT();
    for (int c = 0; c < NC; c++) {
        const int p = c & 1;
        if (c + 1 < NC) {
            load_chunk(sb + ((c + 1) & 1) * BUFSZ, t, Ah, Al, lda, Bh, Bl, ldb, (c + 1) * 32);
            CP_COMMIT();
            CP_WAIT1();
        } else {
            CP_WAIT0();
        }
        __syncthreads();
        compute_chunk(sb + p * BUFSZ, wm, wn, lane, acc);
        __syncthreads();
    }
}

// ===========================================================================
// elementwise kernels
// ===========================================================================
__global__ void zero_colsum_kernel() {
    int i = blockIdx.x * blockDim.x + threadIdx.x;
    if (i < BATCH * SEQ) g_colsum[i] = 0.0f;
}

__global__ void split_kernel(const float* __restrict__ src,
                             __nv_bfloat16* __restrict__ H,
                             __nv_bfloat16* __restrict__ L, int n8) {
    int i = blockIdx.x * blockDim.x + threadIdx.x;
    if (i >= n8) return;
    const float4* p = (const float4*)src + (size_t)i * 2;
    float4 a = p[0], b = p[1];
    float x[8] = {a.x, a.y, a.z, a.w, b.x, b.y, b.z, b.w};
    uint4 Hp, Lp;
    split_pack8(x, Hp, Lp);
    ((uint4*)H)[i] = Hp;
    ((uint4*)L)[i] = Lp;
}

__global__ void copy_in_kernel(const float* __restrict__ X, float* __restrict__ out) {
    const int i4 = blockIdx.x * blockDim.x + threadIdx.x;
    const int row = i4 >> 7;
    const int c4  = i4 & 127;
    ((float4*)out)[(size_t)row * (OUTC / 4) + c4] = ((const float4*)X)[i4];
}

// vt[b, v, i] = split( v[b, i, v] / colsum[b, i] )
__global__ void scale_v_t_kernel() {
    __shared__ float ts[32][33];
    const int b  = blockIdx.z;
    const int i0 = blockIdx.x * 32;
    const int v0 = blockIdx.y * 32;
    const int tx = threadIdx.x, ty = threadIdx.y;  // 32 x 8
    const float* V = g_v + (size_t)b * SEQ * VSZ;
#pragma unroll
    for (int r = 0; r < 32; r += 8) {
        int i = i0 + r + ty;
        float inv = 1.0f / g_colsum[b * SEQ + i];
        ts[r + ty][tx] = V[(size_t)i * VSZ + v0 + tx] * inv;
    }
    __syncthreads();
    __nv_bfloat16* H = g_vth + ((size_t)b * VSZ + v0) * SEQ + i0;
    __nv_bfloat16* L = g_vtl + ((size_t)b * VSZ + v0) * SEQ + i0;
#pragma unroll
    for (int r = 0; r < 32; r += 8) {
        int v = r + ty;
        float x = ts[tx][v];
        __nv_bfloat16 h = __float2bfloat16_rn(x);
        __nv_bfloat16 l = __float2bfloat16_rn(x - __bfloat162float(h));
        H[(size_t)v * SEQ + tx] = h;
        L[(size_t)v * SEQ + tx] = l;
    }
}

// ===========================================================================
// GEMM 1: projections  Y = X @ W^T + b   (z: 0=q, 1=k -> planes; 2=v -> fp32)
// ===========================================================================
__global__ __launch_bounds__(512, 1) void proj_mma(
    const float* __restrict__ bq, const float* __restrict__ bk,
    const float* __restrict__ bv)
{
    extern __shared__ char smem[];
    const uint32_t sb = smem_u32(smem);
    const int t = threadIdx.x;
    const int z  = blockIdx.z;
    const int m0 = blockIdx.y * 128;
    const int n0 = blockIdx.x * 128;
    const float* bias = (z == 0) ? bq : (z == 1) ? bk : bv;

    float* sbias = (float*)(smem + SM_AUX);
    if (t < 128) sbias[t] = bias[n0 + t];

    float acc[2][4][4] = {};
    gemm_loop(sb, t,
              g_xh + (size_t)m0 * CH, g_xl + (size_t)m0 * CH, CH,
              g_wh + (size_t)z * CH * CH + (size_t)n0 * CH,
              g_wl + (size_t)z * CH * CH + (size_t)n0 * CH, CH,
              CH / 32, acc);

    const int wid = t >> 5, lane = t & 31;
    const int wm = wid & 3, wn = wid >> 2;
    const int g = lane >> 2, q = lane & 3;

#pragma unroll
    for (int m2 = 0; m2 < 2; m2++) {
        const int r0 = m0 + wm * 32 + m2 * 16 + g;
#pragma unroll
        for (int n = 0; n < 4; n++) {
            const int cl = wn * 32 + n * 8 + 2 * q;
            const float b0 = sbias[cl], b1 = sbias[cl + 1];
            float v00 = acc[m2][n][0] + b0, v01 = acc[m2][n][1] + b1;
            float v10 = acc[m2][n][2] + b0, v11 = acc[m2][n][3] + b1;
            if (z == 2) {
                float* p0 = g_v + (size_t)r0 * VSZ + n0 + cl;
                float* p1 = g_v + (size_t)(r0 + 8) * VSZ + n0 + cl;
                *(float2*)p0 = make_float2(v00, v01);
                *(float2*)p1 = make_float2(v10, v11);
            } else {
                __nv_bfloat16* H = (z == 0) ? g_qh : g_kh;
                __nv_bfloat16* L = (z == 0) ? g_ql : g_kl;
                uint32_t h0, l0, h1, l1;
                split2(v00, v01, h0, l0);
                split2(v10, v11, h1, l1);
                *(uint32_t*)(H + (size_t)r0 * KSZ + n0 + cl)       = h0;
                *(uint32_t*)(L + (size_t)r0 * KSZ + n0 + cl)       = l0;
                *(uint32_t*)(H + (size_t)(r0 + 8) * KSZ + n0 + cl) = h1;
                *(uint32_t*)(L + (size_t)(r0 + 8) * KSZ + n0 + cl) = l1;
            }
        }
    }
}

// ===========================================================================
// GEMM 2: scores  E = exp(mask(Q K^T * scale)), colsum atomics
// grid (ix, jy, b): only lower-tri tiles (ix <= jy) do work
// ===========================================================================
__global__ __launch_bounds__(512, 1) void scores_mma()
{
    if (blockIdx.x > blockIdx.y) return;
    extern __shared__ char smem[];
    const uint32_t sb = smem_u32(smem);
    const int t = threadIdx.x;
    const int b  = blockIdx.z;
    const int i0 = blockIdx.x * 128;
    const int j0 = blockIdx.y * 128;

    float* scol = (float*)(smem + SM_AUX);
    if (t < 128) scol[t] = 0.0f;

    float acc[2][4][4] = {};
    gemm_loop(sb, t,
              g_qh + ((size_t)b * SEQ + j0) * KSZ, g_ql + ((size_t)b * SEQ + j0) * KSZ, KSZ,
              g_kh + ((size_t)b * SEQ + i0) * KSZ, g_kl + ((size_t)b * SEQ + i0) * KSZ, KSZ,
              KSZ / 32, acc);

    const int wid = t >> 5, lane = t & 31;
    const int wm = wid & 3, wn = wid >> 2;
    const int g = lane >> 2, q = lane & 3;

    __nv_bfloat16* EH = g_eh + (size_t)b * SEQ * SEQ;
    __nv_bfloat16* EL = g_el + (size_t)b * SEQ * SEQ;

    float ev[2][4][4];
#pragma unroll
    for (int m2 = 0; m2 < 2; m2++) {
        const int j = j0 + wm * 32 + m2 * 16 + g;
#pragma unroll
        for (int n = 0; n < 4; n++) {
            const int c = i0 + wn * 32 + n * 8 + 2 * q;
            ev[m2][n][0] = (c     <= j)     ? __expf(acc[m2][n][0] * SCALE) : 0.0f;
            ev[m2][n][1] = (c + 1 <= j)     ? __expf(acc[m2][n][1] * SCALE) : 0.0f;
            ev[m2][n][2] = (c     <= j + 8) ? __expf(acc[m2][n][2] * SCALE) : 0.0f;
            ev[m2][n][3] = (c + 1 <= j + 8) ? __expf(acc[m2][n][3] * SCALE) : 0.0f;

            uint32_t h0, l0, h1, l1;
            split2(ev[m2][n][0], ev[m2][n][1], h0, l0);
            split2(ev[m2][n][2], ev[m2][n][3], h1, l1);
            *(uint32_t*)(EH + (size_t)j * SEQ + c)       = h0;
            *(uint32_t*)(EL + (size_t)j * SEQ + c)       = l0;
            *(uint32_t*)(EH + (size_t)(j + 8) * SEQ + c) = h1;
            *(uint32_t*)(EL + (size_t)(j + 8) * SEQ + c) = l1;
        }
    }

    // column sums: reduce the 32 warp-tile rows per column, then one atomic
#pragma unroll
    for (int n = 0; n < 4; n++)
#pragma unroll
        for (int d = 0; d < 2; d++) {
            float s = ev[0][n][d] + ev[0][n][d + 2] + ev[1][n][d] + ev[1][n][d + 2];
            s += __shfl_xor_sync(0xFFFFFFFF, s, 4);
            s += __shfl_xor_sync(0xFFFFFFFF, s, 8);
            s += __shfl_xor_sync(0xFFFFFFFF, s, 16);
            if (lane < 4) atomicAdd(&scol[wn * 32 + n * 8 + 2 * lane + d], s);
        }
    __syncthreads();
    if (t < 128) atomicAdd(&g_colsum[b * SEQ + i0 + t], scol[t]);
}

// ===========================================================================
// GEMM 3: read = E @ Vsc^T -> out[:, 512:1024], K truncated at diag tile
// ===========================================================================
__global__ __launch_bounds__(512, 1) void read_mma(float* __restrict__ out)
{
    extern __shared__ char smem[];
    const uint32_t sb = smem_u32(smem);
    const int t = threadIdx.x;
    const int b  = blockIdx.z;
    const int n0 = blockIdx.x * 128;
    const int m0 = blockIdx.y * 128;

    float acc[2][4][4] = {};
    gemm_loop(sb, t,
              g_eh + (size_t)b * SEQ * SEQ + (size_t)m0 * SEQ,
              g_el + (size_t)b * SEQ * SEQ + (size_t)m0 * SEQ, SEQ,
              g_vth + ((size_t)b * VSZ + n0) * SEQ,
              g_vtl + ((size_t)b * VSZ + n0) * SEQ, SEQ,
              4 * (blockIdx.y + 1), acc);

    const int wid = t >> 5, lane = t & 31;
    const int wm = wid & 3, wn = wid >> 2;
    const int g = lane >> 2, q = lane & 3;

#pragma unroll
    for (int m2 = 0; m2 < 2; m2++) {
        const int j = m0 + wm * 32 + m2 * 16 + g;
        float* row0 = out + ((size_t)b * SEQ + j) * OUTC + CH + n0;
        float* row1 = row0 + (size_t)8 * OUTC;
#pragma unroll
        for (int n = 0; n < 4; n++) {
            const int cl = wn * 32 + n * 8 + 2 * q;
            *(float2*)(row0 + cl) = make_float2(acc[m2][n][0], acc[m2][n][1]);
            *(float2*)(row1 + cl) = make_float2(acc[m2][n][2], acc[m2][n][3]);
        }
    }
}

// ===========================================================================
extern "C" void kernel_launch(void* const* d_in, const int* in_sizes, int n_in,
                              void* d_out, int out_size)
{
    const float* X  = (const float*)d_in[0];
    const float* Wq = (const float*)d_in[1];
    const float* bq = (const float*)d_in[2];
    const float* Wk = (const float*)d_in[3];
    const float* bk = (const float*)d_in[4];
    const float* Wv = (const float*)d_in[5];
    const float* bv = (const float*)d_in[6];
    float* out = (float*)d_out;

    __nv_bfloat16 *xh, *xl, *wh, *wl;
    cudaGetSymbolAddress((void**)&xh, g_xh);
    cudaGetSymbolAddress((void**)&xl, g_xl);
    cudaGetSymbolAddress((void**)&wh, g_wh);
    cudaGetSymbolAddress((void**)&wl, g_wl);

    cudaFuncSetAttribute(proj_mma,   cudaFuncAttributeMaxDynamicSharedMemorySize, SMEM_BYTES);
    cudaFuncSetAttribute(scores_mma, cudaFuncAttributeMaxDynamicSharedMemorySize, SMEM_BYTES);
    cudaFuncSetAttribute(read_mma,   cudaFuncAttributeMaxDynamicSharedMemorySize, SMEM_BYTES);

    zero_colsum_kernel<<<(BATCH * SEQ + 255) / 256, 256>>>();

    const int nx8 = MROWS * CH / 8;
    split_kernel<<<(nx8 + 255) / 256, 256>>>(X, xh, xl, nx8);
    const int nw8 = CH * CH / 8;
    split_kernel<<<(nw8 + 255) / 256, 256>>>(Wq, wh,           wl,           nw8);
    split_kernel<<<(nw8 + 255) / 256, 256>>>(Wk, wh + CH * CH, wl + CH * CH, nw8);
    split_kernel<<<(nw8 + 255) / 256, 256>>>(Wv, wh + 2 * CH * CH, wl + 2 * CH * CH, nw8);

    proj_mma<<<dim3(4, 128, 3), 512, SMEM_BYTES>>>(bq, bk, bv);
    scores_mma<<<dim3(16, 16, BATCH), 512, SMEM_BYTES>>>();
    scale_v_t_kernel<<<dim3(SEQ / 32, VSZ / 32, BATCH), dim3(32, 8)>>>();
    read_mma<<<dim3(4, 16, BATCH), 512, SMEM_BYTES>>>(out);
    copy_in_kernel<<<(BATCH * SEQ * CH / 4) / 256, 256>>>(X, out);
}

// round 6
// speedup vs baseline: 1.0024x; 1.0024x over previous
#include <cuda_runtime.h>
#include <cuda_bf16.h>
#include <cstdint>
#include <math.h>

#define BATCH 8
#define SEQ   2048
#define CH    512
#define KSZ   512
#define VSZ   512
#define OUTC  1024
#define MROWS (BATCH * SEQ)
#define SCALE 0.044194173824159216f  /* 1/sqrt(512) */

// ------------------------- scratch (static device) -------------------------
static __device__ __nv_bfloat16 g_xh[(size_t)MROWS * CH];
static __device__ __nv_bfloat16 g_xl[(size_t)MROWS * CH];
static __device__ __nv_bfloat16 g_wh[3 * CH * CH];
static __device__ __nv_bfloat16 g_wl[3 * CH * CH];
static __device__ __nv_bfloat16 g_qh[(size_t)MROWS * KSZ];
static __device__ __nv_bfloat16 g_ql[(size_t)MROWS * KSZ];
static __device__ __nv_bfloat16 g_kh[(size_t)MROWS * KSZ];
static __device__ __nv_bfloat16 g_kl[(size_t)MROWS * KSZ];
static __device__ float         g_v [(size_t)MROWS * VSZ];
static __device__ __nv_bfloat16 g_vth[(size_t)BATCH * VSZ * SEQ];  // transposed V/colsum
static __device__ __nv_bfloat16 g_vtl[(size_t)BATCH * VSZ * SEQ];
static __device__ __nv_bfloat16 g_eh[(size_t)BATCH * SEQ * SEQ];
static __device__ __nv_bfloat16 g_el[(size_t)BATCH * SEQ * SEQ];
static __device__ float         g_colsum[BATCH * SEQ];

// ------------------------- smem layout ------------------------------------
// two buffers of 4 planes (Ah, Al, Bh, Bl), each plane [128][40] bf16 = 10240B
#define PL      10240
#define BUFSZ   40960
#define SM_AUX  (2 * BUFSZ)          // 512 B: bias / column sums
#define SMEM_BYTES (2 * BUFSZ + 512)
#define LDS_S   40                    // padded smem row stride (elements)

// ------------------------- ptx helpers ------------------------------------
__device__ __forceinline__ uint32_t smem_u32(const void* p) {
    uint32_t a;
    asm("{ .reg .u64 t; cvta.to.shared.u64 t, %1; cvt.u32.u64 %0, t; }" : "=r"(a) : "l"(p));
    return a;
}

#define CP_ASYNC16(dst, src) \
    asm volatile("cp.async.cg.shared.global [%0], [%1], 16;" :: "r"(dst), "l"(src))
#define CP_COMMIT()  asm volatile("cp.async.commit_group;")
#define CP_WAIT1()   asm volatile("cp.async.wait_group 1;")
#define CP_WAIT0()   asm volatile("cp.async.wait_group 0;")

#define LDSM4(r, a) \
    asm volatile("ldmatrix.sync.aligned.m8n8.x4.shared.b16 {%0,%1,%2,%3}, [%4];" \
                 : "=r"((r)[0]), "=r"((r)[1]), "=r"((r)[2]), "=r"((r)[3]) : "r"(a))

__device__ __forceinline__ void mma16816(float* c, const uint32_t* a, uint32_t b0, uint32_t b1) {
    asm volatile(
        "mma.sync.aligned.m16n8k16.row.col.f32.bf16.bf16.f32 "
        "{%0,%1,%2,%3}, {%4,%5,%6,%7}, {%8,%9}, {%0,%1,%2,%3};"
        : "+f"(c[0]), "+f"(c[1]), "+f"(c[2]), "+f"(c[3])
        : "r"(a[0]), "r"(a[1]), "r"(a[2]), "r"(a[3]), "r"(b0), "r"(b1));
}

// split fp32 -> (hi, lo) bf16
__device__ __forceinline__ void split2(float x, float y, uint32_t& H, uint32_t& L) {
    __nv_bfloat16 hx = __float2bfloat16_rn(x);
    __nv_bfloat16 hy = __float2bfloat16_rn(y);
    __nv_bfloat16 lx = __float2bfloat16_rn(x - __bfloat162float(hx));
    __nv_bfloat16 ly = __float2bfloat16_rn(y - __bfloat162float(hy));
    H = (uint32_t)__bfloat16_as_ushort(hx) | ((uint32_t)__bfloat16_as_ushort(hy) << 16);
    L = (uint32_t)__bfloat16_as_ushort(lx) | ((uint32_t)__bfloat16_as_ushort(ly) << 16);
}

__device__ __forceinline__ void split_pack8(const float* x, uint4& H, uint4& L) {
    uint32_t h[4], l[4];
#pragma unroll
    for (int q = 0; q < 4; q++) split2(x[2 * q], x[2 * q + 1], h[q], l[q]);
    H = make_uint4(h[0], h[1], h[2], h[3]);
    L = make_uint4(l[0], l[1], l[2], l[3]);
}

// ---------------------------------------------------------------------------
// chunk loader: 512 threads, 4 planes x 128 rows x 64B (k-chunk = 32 bf16)
// ---------------------------------------------------------------------------
__device__ __forceinline__ void load_chunk(
    uint32_t sbuf, int t,
    const __nv_bfloat16* Ah, const __nv_bfloat16* Al, int lda,
    const __nv_bfloat16* Bh, const __nv_bfloat16* Bl, int ldb, int k0)
{
    const int row = t >> 2, seg = t & 3;
    const size_t goA = (size_t)row * lda + k0 + seg * 8;
    const size_t goB = (size_t)row * ldb + k0 + seg * 8;
    const uint32_t so = sbuf + row * (LDS_S * 2) + seg * 16;
    CP_ASYNC16(so,          Ah + goA);
    CP_ASYNC16(so + PL,     Al + goA);
    CP_ASYNC16(so + 2 * PL, Bh + goB);
    CP_ASYNC16(so + 3 * PL, Bl + goB);
}

// ---------------------------------------------------------------------------
// compute one 32-K chunk: warp tile 32x32, bf16x3 (hh + hl + lh)
// ---------------------------------------------------------------------------
__device__ __forceinline__ void compute_chunk(
    uint32_t sbuf, int wm, int wn, int lane, float acc[2][4][4])
{
    const int lm = lane & 15, lk = lane >> 4;
#pragma unroll
    for (int ks = 0; ks < 2; ks++) {
        uint32_t ah[2][4], al[2][4];
#pragma unroll
        for (int m2 = 0; m2 < 2; m2++) {
            uint32_t ad = sbuf + (wm * 32 + m2 * 16 + lm) * (LDS_S * 2) + (ks * 16 + lk * 8) * 2;
            LDSM4(ah[m2], ad);
            LDSM4(al[m2], ad + PL);
        }
        uint32_t bh[2][4], bl[2][4];
#pragma unroll
        for (int np = 0; np < 2; np++) {
            uint32_t bd = sbuf + 2 * PL + (wn * 32 + np * 16 + lm) * (LDS_S * 2) + (ks * 16 + lk * 8) * 2;
            LDSM4(bh[np], bd);
            LDSM4(bl[np], bd + PL);
        }
#pragma unroll
        for (int m2 = 0; m2 < 2; m2++)
#pragma unroll
            for (int n = 0; n < 4; n++) {
                const int np = n >> 1, sel = n & 1;
                mma16816(acc[m2][n], ah[m2], bh[np][sel], bh[np][sel + 2]);
                mma16816(acc[m2][n], ah[m2], bl[np][sel], bl[np][sel + 2]);
                mma16816(acc[m2][n], al[m2], bh[np][sel], bh[np][sel + 2]);
            }
    }
}

// ---------------------------------------------------------------------------
// full double-buffered mainloop
// ---------------------------------------------------------------------------
__device__ __forceinline__ void gemm_loop(
    uint32_t sb, int t,
    const __nv_bfloat16* Ah, const __nv_bfloat16* Al, int lda,
    const __nv_bfloat16* Bh, const __nv_bfloat16* Bl, int ldb,
    int NC, float acc[2][4][4])
{
    const int wid = t >> 5, lane = t & 31;
    const int wm = wid & 3, wn = wid >> 2;

    load_chunk(sb, t, Ah, Al, lda, Bh, Bl, ldb, 0);
    CP_COMMIT();
    for (int c = 0; c < NC; c++) {
        const int p = c & 1;
        if (c + 1 < NC) {
            load_chunk(sb + ((c + 1) & 1) * BUFSZ, t, Ah, Al, lda, Bh, Bl, ldb, (c + 1) * 32);
            CP_COMMIT();
            CP_WAIT1();
        } else {
            CP_WAIT0();
        }
        __syncthreads();
        compute_chunk(sb + p * BUFSZ, wm, wn, lane, acc);
        __syncthreads();
    }
}

// ===========================================================================
// elementwise kernels
// ===========================================================================
__global__ void zero_colsum_kernel() {
    int i = blockIdx.x * blockDim.x + threadIdx.x;
    if (i < BATCH * SEQ) g_colsum[i] = 0.0f;
}

__global__ void split_kernel(const float* __restrict__ src,
                             __nv_bfloat16* __restrict__ H,
                             __nv_bfloat16* __restrict__ L, int n8) {
    int i = blockIdx.x * blockDim.x + threadIdx.x;
    if (i >= n8) return;
    const float4* p = (const float4*)src + (size_t)i * 2;
    float4 a = p[0], b = p[1];
    float x[8] = {a.x, a.y, a.z, a.w, b.x, b.y, b.z, b.w};
    uint4 Hp, Lp;
    split_pack8(x, Hp, Lp);
    ((uint4*)H)[i] = Hp;
    ((uint4*)L)[i] = Lp;
}

__global__ void copy_in_kernel(const float* __restrict__ X, float* __restrict__ out) {
    const int i4 = blockIdx.x * blockDim.x + threadIdx.x;
    const int row = i4 >> 7;
    const int c4  = i4 & 127;
    ((float4*)out)[(size_t)row * (OUTC / 4) + c4] = ((const float4*)X)[i4];
}

// vt[b, v, i] = split( v[b, i, v] / colsum[b, i] )
__global__ void scale_v_t_kernel() {
    __shared__ float ts[32][33];
    const int b  = blockIdx.z;
    const int i0 = blockIdx.x * 32;
    const int v0 = blockIdx.y * 32;
    const int tx = threadIdx.x, ty = threadIdx.y;  // 32 x 8
    const float* V = g_v + (size_t)b * SEQ * VSZ;
#pragma unroll
    for (int r = 0; r < 32; r += 8) {
        int i = i0 + r + ty;
        float inv = 1.0f / g_colsum[b * SEQ + i];
        ts[r + ty][tx] = V[(size_t)i * VSZ + v0 + tx] * inv;
    }
    __syncthreads();
    __nv_bfloat16* H = g_vth + ((size_t)b * VSZ + v0) * SEQ + i0;
    __nv_bfloat16* L = g_vtl + ((size_t)b * VSZ + v0) * SEQ + i0;
#pragma unroll
    for (int r = 0; r < 32; r += 8) {
        int v = r + ty;
        float x = ts[tx][v];
        __nv_bfloat16 h = __float2bfloat16_rn(x);
        __nv_bfloat16 l = __float2bfloat16_rn(x - __bfloat162float(h));
        H[(size_t)v * SEQ + tx] = h;
        L[(size_t)v * SEQ + tx] = l;
    }
}

// ===========================================================================
// GEMM 1: projections  Y = X @ W^T + b   (z: 0=q, 1=k -> planes; 2=v -> fp32)
// ===========================================================================
__global__ __launch_bounds__(512, 1) void proj_mma(
    const float* __restrict__ bq, const float* __restrict__ bk,
    const float* __restrict__ bv)
{
    extern __shared__ char smem[];
    const uint32_t sb = smem_u32(smem);
    const int t = threadIdx.x;
    const int z  = blockIdx.z;
    const int m0 = blockIdx.y * 128;
    const int n0 = blockIdx.x * 128;
    const float* bias = (z == 0) ? bq : (z == 1) ? bk : bv;

    float* sbias = (float*)(smem + SM_AUX);
    if (t < 128) sbias[t] = bias[n0 + t];

    float acc[2][4][4] = {};
    gemm_loop(sb, t,
              g_xh + (size_t)m0 * CH, g_xl + (size_t)m0 * CH, CH,
              g_wh + (size_t)z * CH * CH + (size_t)n0 * CH,
              g_wl + (size_t)z * CH * CH + (size_t)n0 * CH, CH,
              CH / 32, acc);

    const int wid = t >> 5, lane = t & 31;
    const int wm = wid & 3, wn = wid >> 2;
    const int g = lane >> 2, q = lane & 3;

#pragma unroll
    for (int m2 = 0; m2 < 2; m2++) {
        const int r0 = m0 + wm * 32 + m2 * 16 + g;
#pragma unroll
        for (int n = 0; n < 4; n++) {
            const int cl = wn * 32 + n * 8 + 2 * q;
            const float b0 = sbias[cl], b1 = sbias[cl + 1];
            float v00 = acc[m2][n][0] + b0, v01 = acc[m2][n][1] + b1;
            float v10 = acc[m2][n][2] + b0, v11 = acc[m2][n][3] + b1;
            if (z == 2) {
                float* p0 = g_v + (size_t)r0 * VSZ + n0 + cl;
                float* p1 = g_v + (size_t)(r0 + 8) * VSZ + n0 + cl;
                *(float2*)p0 = make_float2(v00, v01);
                *(float2*)p1 = make_float2(v10, v11);
            } else {
                __nv_bfloat16* H = (z == 0) ? g_qh : g_kh;
                __nv_bfloat16* L = (z == 0) ? g_ql : g_kl;
                uint32_t h0, l0, h1, l1;
                split2(v00, v01, h0, l0);
                split2(v10, v11, h1, l1);
                *(uint32_t*)(H + (size_t)r0 * KSZ + n0 + cl)       = h0;
                *(uint32_t*)(L + (size_t)r0 * KSZ + n0 + cl)       = l0;
                *(uint32_t*)(H + (size_t)(r0 + 8) * KSZ + n0 + cl) = h1;
                *(uint32_t*)(L + (size_t)(r0 + 8) * KSZ + n0 + cl) = l1;
            }
        }
    }
}

// ===========================================================================
// GEMM 2: scores  E = exp(mask(Q K^T * scale)), colsum atomics
// grid (ix, jy, b): only lower-tri tiles (ix <= jy) do work
// ===========================================================================
__global__ __launch_bounds__(512, 1) void scores_mma()
{
    if (blockIdx.x > blockIdx.y) return;
    extern __shared__ char smem[];
    const uint32_t sb = smem_u32(smem);
    const int t = threadIdx.x;
    const int b  = blockIdx.z;
    const int i0 = blockIdx.x * 128;
    const int j0 = blockIdx.y * 128;

    float* scol = (float*)(smem + SM_AUX);
    if (t < 128) scol[t] = 0.0f;

    float acc[2][4][4] = {};
    gemm_loop(sb, t,
              g_qh + ((size_t)b * SEQ + j0) * KSZ, g_ql + ((size_t)b * SEQ + j0) * KSZ, KSZ,
              g_kh + ((size_t)b * SEQ + i0) * KSZ, g_kl + ((size_t)b * SEQ + i0) * KSZ, KSZ,
              KSZ / 32, acc);

    const int wid = t >> 5, lane = t & 31;
    const int wm = wid & 3, wn = wid >> 2;
    const int g = lane >> 2, q = lane & 3;

    __nv_bfloat16* EH = g_eh + (size_t)b * SEQ * SEQ;
    __nv_bfloat16* EL = g_el + (size_t)b * SEQ * SEQ;

    float ev[2][4][4];
#pragma unroll
    for (int m2 = 0; m2 < 2; m2++) {
        const int j = j0 + wm * 32 + m2 * 16 + g;
#pragma unroll
        for (int n = 0; n < 4; n++) {
            const int c = i0 + wn * 32 + n * 8 + 2 * q;
            ev[m2][n][0] = (c     <= j)     ? __expf(acc[m2][n][0] * SCALE) : 0.0f;
            ev[m2][n][1] = (c + 1 <= j)     ? __expf(acc[m2][n][1] * SCALE) : 0.0f;
            ev[m2][n][2] = (c     <= j + 8) ? __expf(acc[m2][n][2] * SCALE) : 0.0f;
            ev[m2][n][3] = (c + 1 <= j + 8) ? __expf(acc[m2][n][3] * SCALE) : 0.0f;

            uint32_t h0, l0, h1, l1;
            split2(ev[m2][n][0], ev[m2][n][1], h0, l0);
            split2(ev[m2][n][2], ev[m2][n][3], h1, l1);
            *(uint32_t*)(EH + (size_t)j * SEQ + c)       = h0;
            *(uint32_t*)(EL + (size_t)j * SEQ + c)       = l0;
            *(uint32_t*)(EH + (size_t)(j + 8) * SEQ + c) = h1;
            *(uint32_t*)(EL + (size_t)(j + 8) * SEQ + c) = l1;
        }
    }

    // column sums: reduce the 32 warp-tile rows per column, then one atomic
#pragma unroll
    for (int n = 0; n < 4; n++)
#pragma unroll
        for (int d = 0; d < 2; d++) {
            float s = ev[0][n][d] + ev[0][n][d + 2] + ev[1][n][d] + ev[1][n][d + 2];
            s += __shfl_xor_sync(0xFFFFFFFF, s, 4);
            s += __shfl_xor_sync(0xFFFFFFFF, s, 8);
            s += __shfl_xor_sync(0xFFFFFFFF, s, 16);
            if (lane < 4) atomicAdd(&scol[wn * 32 + n * 8 + 2 * lane + d], s);
        }
    __syncthreads();
    if (t < 128) atomicAdd(&g_colsum[b * SEQ + i0 + t], scol[t]);
}

// ===========================================================================
// GEMM 3: read = E @ Vsc^T -> out[:, 512:1024], K truncated at diag tile
// ===========================================================================
__global__ __launch_bounds__(512, 1) void read_mma(float* __restrict__ out)
{
    extern __shared__ char smem[];
    const uint32_t sb = smem_u32(smem);
    const int t = threadIdx.x;
    const int b  = blockIdx.z;
    const int n0 = blockIdx.x * 128;
    const int m0 = blockIdx.y * 128;

    float acc[2][4][4] = {};
    gemm_loop(sb, t,
              g_eh + (size_t)b * SEQ * SEQ + (size_t)m0 * SEQ,
              g_el + (size_t)b * SEQ * SEQ + (size_t)m0 * SEQ, SEQ,
              g_vth + ((size_t)b * VSZ + n0) * SEQ,
              g_vtl + ((size_t)b * VSZ + n0) * SEQ, SEQ,
              4 * (blockIdx.y + 1), acc);

    const int wid = t >> 5, lane = t & 31;
    const int wm = wid & 3, wn = wid >> 2;
    const int g = lane >> 2, q = lane & 3;

#pragma unroll
    for (int m2 = 0; m2 < 2; m2++) {
        const int j = m0 + wm * 32 + m2 * 16 + g;
        float* row0 = out + ((size_t)b * SEQ + j) * OUTC + CH + n0;
        float* row1 = row0 + (size_t)8 * OUTC;
#pragma unroll
        for (int n = 0; n < 4; n++) {
            const int cl = wn * 32 + n * 8 + 2 * q;
            *(float2*)(row0 + cl) = make_float2(acc[m2][n][0], acc[m2][n][1]);
            *(float2*)(row1 + cl) = make_float2(acc[m2][n][2], acc[m2][n][3]);
        }
    }
}

// ===========================================================================
extern "C" void kernel_launch(void* const* d_in, const int* in_sizes, int n_in,
                              void* d_out, int out_size)
{
    const float* X  = (const float*)d_in[0];
    const float* Wq = (const float*)d_in[1];
    const float* bq = (const float*)d_in[2];
    const float* Wk = (const float*)d_in[3];
    const float* bk = (const float*)d_in[4];
    const float* Wv = (const float*)d_in[5];
    const float* bv = (const float*)d_in[6];
    float* out = (float*)d_out;

    __nv_bfloat16 *xh, *xl, *wh, *wl;
    cudaGetSymbolAddress((void**)&xh, g_xh);
    cudaGetSymbolAddress((void**)&xl, g_xl);
    cudaGetSymbolAddress((void**)&wh, g_wh);
    cudaGetSymbolAddress((void**)&wl, g_wl);

    cudaFuncSetAttribute(proj_mma,   cudaFuncAttributeMaxDynamicSharedMemorySize, SMEM_BYTES);
    cudaFuncSetAttribute(scores_mma, cudaFuncAttributeMaxDynamicSharedMemorySize, SMEM_BYTES);
    cudaFuncSetAttribute(read_mma,   cudaFuncAttributeMaxDynamicSharedMemorySize, SMEM_BYTES);

    zero_colsum_kernel<<<(BATCH * SEQ + 255) / 256, 256>>>();

    const int nx8 = MROWS * CH / 8;
    split_kernel<<<(nx8 + 255) / 256, 256>>>(X, xh, xl, nx8);
    const int nw8 = CH * CH / 8;
    split_kernel<<<(nw8 + 255) / 256, 256>>>(Wq, wh,           wl,           nw8);
    split_kernel<<<(nw8 + 255) / 256, 256>>>(Wk, wh + CH * CH, wl + CH * CH, nw8);
    split_kernel<<<(nw8 + 255) / 256, 256>>>(Wv, wh + 2 * CH * CH, wl + 2 * CH * CH, nw8);

    proj_mma<<<dim3(4, 128, 3), 512, SMEM_BYTES>>>(bq, bk, bv);
    scores_mma<<<dim3(16, 16, BATCH), 512, SMEM_BYTES>>>();
    scale_v_t_kernel<<<dim3(SEQ / 32, VSZ / 32, BATCH), dim3(32, 8)>>>();
    read_mma<<<dim3(4, 16, BATCH), 512, SMEM_BYTES>>>(out);
    copy_in_kernel<<<(BATCH * SEQ * CH / 4) / 256, 256>>>(X, out);
}

// round 7
// speedup vs baseline: 1.7312x; 1.7271x over previous
#include <cuda_runtime.h>
#include <cuda_fp16.h>
#include <cstdint>
#include <math.h>

#define BATCH 8
#define SEQ   2048
#define CH    512
#define KSZ   512
#define VSZ   512
#define OUTC  1024
#define MROWS (BATCH * SEQ)
#define SCALE 0.044194173824159216f  /* 1/sqrt(512), folded into q */

// ------------------------- scratch (static device) -------------------------
static __device__ __half g_x [(size_t)MROWS * CH];
static __device__ __half g_w [3 * CH * CH];
static __device__ __half g_q [(size_t)MROWS * KSZ];     // pre-scaled by SCALE
static __device__ __half g_k [(size_t)MROWS * KSZ];
static __device__ float  g_v [(size_t)MROWS * VSZ];
static __device__ __half g_vt[(size_t)BATCH * VSZ * SEQ];  // transposed V/colsum
static __device__ __half g_e [(size_t)BATCH * SEQ * SEQ];
static __device__ float  g_colsum[BATCH * SEQ];

// ------------------------- smem layout ------------------------------------
// K-chunk 64: plane [128][72] half = 18432 B; buffer = A+B planes; x2 buffers
#define LDS_B   144                   // padded row stride (bytes) = 72 halves
#define PL      18432
#define BUFSZ   (2 * PL)
#define SM_AUX  (2 * BUFSZ)
#define SMEM_BYTES (2 * BUFSZ + 512)

// ------------------------- ptx helpers ------------------------------------
__device__ __forceinline__ uint32_t smem_u32(const void* p) {
    uint32_t a;
    asm("{ .reg .u64 t; cvta.to.shared.u64 t, %1; cvt.u32.u64 %0, t; }" : "=r"(a) : "l"(p));
    return a;
}

#define CP_ASYNC16(dst, src) \
    asm volatile("cp.async.cg.shared.global [%0], [%1], 16;" :: "r"(dst), "l"(src))
#define CP_COMMIT()  asm volatile("cp.async.commit_group;")
#define CP_WAIT1()   asm volatile("cp.async.wait_group 1;")
#define CP_WAIT0()   asm volatile("cp.async.wait_group 0;")

#define LDSM4(r, a) \
    asm volatile("ldmatrix.sync.aligned.m8n8.x4.shared.b16 {%0,%1,%2,%3}, [%4];" \
                 : "=r"((r)[0]), "=r"((r)[1]), "=r"((r)[2]), "=r"((r)[3]) : "r"(a))

__device__ __forceinline__ void mma16816(float* c, const uint32_t* a, uint32_t b0, uint32_t b1) {
    asm volatile(
        "mma.sync.aligned.m16n8k16.row.col.f32.f16.f16.f32 "
        "{%0,%1,%2,%3}, {%4,%5,%6,%7}, {%8,%9}, {%0,%1,%2,%3};"
        : "+f"(c[0]), "+f"(c[1]), "+f"(c[2]), "+f"(c[3])
        : "r"(a[0]), "r"(a[1]), "r"(a[2]), "r"(a[3]), "r"(b0), "r"(b1));
}

__device__ __forceinline__ uint32_t pack_h2(float x, float y) {
    __half2 h = __floats2half2_rn(x, y);
    return *(uint32_t*)&h;
}

// ---------------------------------------------------------------------------
// chunk loader: 512 threads, 2 planes x 128 rows x 128B (k-chunk = 64 half)
// row = t&127, seg = t>>7 -> conflict-free smem writes (16B, 8 rows/phase)
// ---------------------------------------------------------------------------
__device__ __forceinline__ void load_chunk(
    uint32_t sbuf, int t,
    const __half* A, int lda, const __half* B, int ldb, int k0)
{
    const int row = t & 127, seg = t >> 7;
    const uint32_t so = sbuf + row * LDS_B + seg * 16;
    const __half* ga = A + (size_t)row * lda + k0 + seg * 8;
    const __half* gb = B + (size_t)row * ldb + k0 + seg * 8;
    CP_ASYNC16(so,           ga);
    CP_ASYNC16(so + 64,      ga + 32);
    CP_ASYNC16(so + PL,      gb);
    CP_ASYNC16(so + PL + 64, gb + 32);
}

// ---------------------------------------------------------------------------
// compute one 64-K chunk: warp tile 32x32, single fp16 plane
// ---------------------------------------------------------------------------
__device__ __forceinline__ void compute_chunk(
    uint32_t sbuf, int wm, int wn, int lane, float acc[2][4][4])
{
    const int lm = lane & 15, lk = lane >> 4;
#pragma unroll
    for (int ks = 0; ks < 4; ks++) {
        const uint32_t koff = ks * 32 + lk * 16;
        uint32_t a[2][4], b[2][4];
#pragma unroll
        for (int m2 = 0; m2 < 2; m2++)
            LDSM4(a[m2], sbuf + (wm * 32 + m2 * 16 + lm) * LDS_B + koff);
#pragma unroll
        for (int np = 0; np < 2; np++)
            LDSM4(b[np], sbuf + PL + (wn * 32 + np * 16 + lm) * LDS_B + koff);
#pragma unroll
        for (int m2 = 0; m2 < 2; m2++)
#pragma unroll
            for (int n = 0; n < 4; n++) {
                const int np = n >> 1, sel = n & 1;
                mma16816(acc[m2][n], a[m2], b[np][sel], b[np][sel + 2]);
            }
    }
}

// ---------------------------------------------------------------------------
// double-buffered mainloop (NC chunks of K=64)
// ---------------------------------------------------------------------------
__device__ __forceinline__ void gemm_loop(
    uint32_t sb, int t,
    const __half* A, int lda, const __half* B, int ldb,
    int NC, float acc[2][4][4])
{
    const int wid = t >> 5, lane = t & 31;
    const int wm = wid & 3, wn = wid >> 2;

    load_chunk(sb, t, A, lda, B, ldb, 0);
    CP_COMMIT();
    for (int c = 0; c < NC; c++) {
        const int p = c & 1;
        if (c + 1 < NC) {
            load_chunk(sb + ((c + 1) & 1) * BUFSZ, t, A, lda, B, ldb, (c + 1) * 64);
            CP_COMMIT();
            CP_WAIT1();
        } else {
            CP_WAIT0();
        }
        __syncthreads();
        compute_chunk(sb + p * BUFSZ, wm, wn, lane, acc);
        __syncthreads();
    }
}

// ===========================================================================
// elementwise kernels
// ===========================================================================
__global__ void zero_colsum_kernel() {
    int i = blockIdx.x * blockDim.x + threadIdx.x;
    if (i < BATCH * SEQ) g_colsum[i] = 0.0f;
}

__global__ void cvt_kernel(const float* __restrict__ src,
                           __half* __restrict__ dst, int n8) {
    int i = blockIdx.x * blockDim.x + threadIdx.x;
    if (i >= n8) return;
    const float4* p = (const float4*)src + (size_t)i * 2;
    float4 a = p[0], b = p[1];
    uint4 o;
    o.x = pack_h2(a.x, a.y);
    o.y = pack_h2(a.z, a.w);
    o.z = pack_h2(b.x, b.y);
    o.w = pack_h2(b.z, b.w);
    ((uint4*)dst)[i] = o;
}

__global__ void copy_in_kernel(const float* __restrict__ X, float* __restrict__ out) {
    const int i4 = blockIdx.x * blockDim.x + threadIdx.x;
    const int row = i4 >> 7;
    const int c4  = i4 & 127;
    ((float4*)out)[(size_t)row * (OUTC / 4) + c4] = ((const float4*)X)[i4];
}

// vt[b, v, i] = half( v[b, i, v] / colsum[b, i] )
__global__ void scale_v_t_kernel() {
    __shared__ float ts[32][33];
    const int b  = blockIdx.z;
    const int i0 = blockIdx.x * 32;
    const int v0 = blockIdx.y * 32;
    const int tx = threadIdx.x, ty = threadIdx.y;  // 32 x 8
    const float* V = g_v + (size_t)b * SEQ * VSZ;
#pragma unroll
    for (int r = 0; r < 32; r += 8) {
        int i = i0 + r + ty;
        float inv = 1.0f / g_colsum[b * SEQ + i];
        ts[r + ty][tx] = V[(size_t)i * VSZ + v0 + tx] * inv;
    }
    __syncthreads();
    __half* H = g_vt + ((size_t)b * VSZ + v0) * SEQ + i0;
#pragma unroll
    for (int r = 0; r < 32; r += 8) {
        int v = r + ty;
        H[(size_t)v * SEQ + tx] = __float2half_rn(ts[tx][v]);
    }
}

// ===========================================================================
// GEMM 1: projections  Y = X @ W^T + b   (z: 0=q*SCALE, 1=k -> fp16; 2=v fp32)
// ===========================================================================
__global__ __launch_bounds__(512, 1) void proj_mma(
    const float* __restrict__ bq, const float* __restrict__ bk,
    const float* __restrict__ bv)
{
    extern __shared__ char smem[];
    const uint32_t sb = smem_u32(smem);
    const int t = threadIdx.x;
    const int z  = blockIdx.z;
    const int m0 = blockIdx.y * 128;
    const int n0 = blockIdx.x * 128;
    const float* bias = (z == 0) ? bq : (z == 1) ? bk : bv;

    float* sbias = (float*)(smem + SM_AUX);
    if (t < 128) sbias[t] = bias[n0 + t];

    float acc[2][4][4] = {};
    gemm_loop(sb, t,
              g_x + (size_t)m0 * CH, CH,
              g_w + (size_t)z * CH * CH + (size_t)n0 * CH, CH,
              CH / 64, acc);

    const int wid = t >> 5, lane = t & 31;
    const int wm = wid & 3, wn = wid >> 2;
    const int g = lane >> 2, q = lane & 3;
    const float mul = (z == 0) ? SCALE : 1.0f;

#pragma unroll
    for (int m2 = 0; m2 < 2; m2++) {
        const int r0 = m0 + wm * 32 + m2 * 16 + g;
#pragma unroll
        for (int n = 0; n < 4; n++) {
            const int cl = wn * 32 + n * 8 + 2 * q;
            const float b0 = sbias[cl], b1 = sbias[cl + 1];
            float v00 = (acc[m2][n][0] + b0) * mul, v01 = (acc[m2][n][1] + b1) * mul;
            float v10 = (acc[m2][n][2] + b0) * mul, v11 = (acc[m2][n][3] + b1) * mul;
            if (z == 2) {
                *(float2*)(g_v + (size_t)r0 * VSZ + n0 + cl)       = make_float2(v00, v01);
                *(float2*)(g_v + (size_t)(r0 + 8) * VSZ + n0 + cl) = make_float2(v10, v11);
            } else {
                __half* H = (z == 0) ? g_q : g_k;
                *(uint32_t*)(H + (size_t)r0 * KSZ + n0 + cl)       = pack_h2(v00, v01);
                *(uint32_t*)(H + (size_t)(r0 + 8) * KSZ + n0 + cl) = pack_h2(v10, v11);
            }
        }
    }
}

// ===========================================================================
// GEMM 2: scores  E = exp(mask(q' k^T)), colsum atomics (SCALE pre-folded)
// ===========================================================================
__global__ __launch_bounds__(512, 1) void scores_mma()
{
    if (blockIdx.x > blockIdx.y) return;
    extern __shared__ char smem[];
    const uint32_t sb = smem_u32(smem);
    const int t = threadIdx.x;
    const int b  = blockIdx.z;
    const int i0 = blockIdx.x * 128;
    const int j0 = blockIdx.y * 128;

    float* scol = (float*)(smem + SM_AUX);
    if (t < 128) scol[t] = 0.0f;

    float acc[2][4][4] = {};
    gemm_loop(sb, t,
              g_q + ((size_t)b * SEQ + j0) * KSZ, KSZ,
              g_k + ((size_t)b * SEQ + i0) * KSZ, KSZ,
              KSZ / 64, acc);

    const int wid = t >> 5, lane = t & 31;
    const int wm = wid & 3, wn = wid >> 2;
    const int g = lane >> 2, q = lane & 3;

    __half* E = g_e + (size_t)b * SEQ * SEQ;

    float ev[2][4][4];
#pragma unroll
    for (int m2 = 0; m2 < 2; m2++) {
        const int j = j0 + wm * 32 + m2 * 16 + g;
#pragma unroll
        for (int n = 0; n < 4; n++) {
            const int c = i0 + wn * 32 + n * 8 + 2 * q;
            ev[m2][n][0] = (c     <= j)     ? __expf(acc[m2][n][0]) : 0.0f;
            ev[m2][n][1] = (c + 1 <= j)     ? __expf(acc[m2][n][1]) : 0.0f;
            ev[m2][n][2] = (c     <= j + 8) ? __expf(acc[m2][n][2]) : 0.0f;
            ev[m2][n][3] = (c + 1 <= j + 8) ? __expf(acc[m2][n][3]) : 0.0f;
            *(uint32_t*)(E + (size_t)j * SEQ + c)       = pack_h2(ev[m2][n][0], ev[m2][n][1]);
            *(uint32_t*)(E + (size_t)(j + 8) * SEQ + c) = pack_h2(ev[m2][n][2], ev[m2][n][3]);
        }
    }

    // column sums: per-column reduce across the warp's 32 rows, then smem atomics
#pragma unroll
    for (int n = 0; n < 4; n++)
#pragma unroll
        for (int d = 0; d < 2; d++) {
            float s = ev[0][n][d] + ev[0][n][d + 2] + ev[1][n][d] + ev[1][n][d + 2];
            s += __shfl_xor_sync(0xFFFFFFFF, s, 4);
            s += __shfl_xor_sync(0xFFFFFFFF, s, 8);
            s += __shfl_xor_sync(0xFFFFFFFF, s, 16);
            if (lane < 4) atomicAdd(&scol[wn * 32 + n * 8 + 2 * lane + d], s);
        }
    __syncthreads();
    if (t < 128) atomicAdd(&g_colsum[b * SEQ + i0 + t], scol[t]);
}

// ===========================================================================
// GEMM 3: read = E @ Vt^T -> out[:, 512:1024], K truncated at diag tile
// ===========================================================================
__global__ __launch_bounds__(512, 1) void read_mma(float* __restrict__ out)
{
    extern __shared__ char smem[];
    const uint32_t sb = smem_u32(smem);
    const int t = threadIdx.x;
    const int b  = blockIdx.z;
    const int n0 = blockIdx.x * 128;
    const int m0 = blockIdx.y * 128;

    float acc[2][4][4] = {};
    gemm_loop(sb, t,
              g_e  + (size_t)b * SEQ * SEQ + (size_t)m0 * SEQ, SEQ,
              g_vt + ((size_t)b * VSZ + n0) * SEQ, SEQ,
              2 * (blockIdx.y + 1), acc);

    const int wid = t >> 5, lane = t & 31;
    const int wm = wid & 3, wn = wid >> 2;
    const int g = lane >> 2, q = lane & 3;

#pragma unroll
    for (int m2 = 0; m2 < 2; m2++) {
        const int j = m0 + wm * 32 + m2 * 16 + g;
        float* row0 = out + ((size_t)b * SEQ + j) * OUTC + CH + n0;
        float* row1 = row0 + (size_t)8 * OUTC;
#pragma unroll
        for (int n = 0; n < 4; n++) {
            const int cl = wn * 32 + n * 8 + 2 * q;
            *(float2*)(row0 + cl) = make_float2(acc[m2][n][0], acc[m2][n][1]);
            *(float2*)(row1 + cl) = make_float2(acc[m2][n][2], acc[m2][n][3]);
        }
    }
}

// ===========================================================================
extern "C" void kernel_launch(void* const* d_in, const int* in_sizes, int n_in,
                              void* d_out, int out_size)
{
    const float* X  = (const float*)d_in[0];
    const float* Wq = (const float*)d_in[1];
    const float* bq = (const float*)d_in[2];
    const float* Wk = (const float*)d_in[3];
    const float* bk = (const float*)d_in[4];
    const float* Wv = (const float*)d_in[5];
    const float* bv = (const float*)d_in[6];
    float* out = (float*)d_out;

    __half *xh, *wh;
    cudaGetSymbolAddress((void**)&xh, g_x);
    cudaGetSymbolAddress((void**)&wh, g_w);

    cudaFuncSetAttribute(proj_mma,   cudaFuncAttributeMaxDynamicSharedMemorySize, SMEM_BYTES);
    cudaFuncSetAttribute(scores_mma, cudaFuncAttributeMaxDynamicSharedMemorySize, SMEM_BYTES);
    cudaFuncSetAttribute(read_mma,   cudaFuncAttributeMaxDynamicSharedMemorySize, SMEM_BYTES);

    zero_colsum_kernel<<<(BATCH * SEQ + 255) / 256, 256>>>();

    const int nx8 = MROWS * CH / 8;
    cvt_kernel<<<(nx8 + 255) / 256, 256>>>(X, xh, nx8);
    const int nw8 = CH * CH / 8;
    cvt_kernel<<<(nw8 + 255) / 256, 256>>>(Wq, wh,              nw8);
    cvt_kernel<<<(nw8 + 255) / 256, 256>>>(Wk, wh + CH * CH,     nw8);
    cvt_kernel<<<(nw8 + 255) / 256, 256>>>(Wv, wh + 2 * CH * CH, nw8);

    proj_mma<<<dim3(4, 128, 3), 512, SMEM_BYTES>>>(bq, bk, bv);
    scores_mma<<<dim3(16, 16, BATCH), 512, SMEM_BYTES>>>();
    scale_v_t_kernel<<<dim3(SEQ / 32, VSZ / 32, BATCH), dim3(32, 8)>>>();
    read_mma<<<dim3(4, 16, BATCH), 512, SMEM_BYTES>>>(out);
    copy_in_kernel<<<(BATCH * SEQ * CH / 4) / 256, 256>>>(X, out);
}